// round 2
// baseline (speedup 1.0000x reference)
#include <cuda_runtime.h>
#include <math.h>

#define TABLE_SIZE 4194304          // 2^22
#define TABLE_MASK (TABLE_SIZE - 1)
#define NVOX (128*128*128)          // 2,097,152
#define NB 1024                     // buckets
#define BSHIFT 12                   // idx >> 12 -> bucket

// ---------------- device-global scratch (allocation-free) ----------------
__device__ double   g_sum;
__device__ double   g_sumsq;
__device__ float    g_mean;
__device__ float    g_inv_std;
__device__ unsigned g_hist[NB];
__device__ unsigned g_cursor[NB];
__device__ uint2    g_records[NVOX];   // (voxel_id, packed coords) 16 MB

__device__ __forceinline__ unsigned hash_idx(int cx, int cy, int cz) {
    unsigned h = (unsigned)cx ^ ((unsigned)cy * 2654435761u)
                             ^ ((unsigned)cz * 805459861u);
    return h & TABLE_MASK;
}

// ---------------- stage 0: zero accumulators + histogram ----------------
__global__ void zero_kernel() {
    int t = threadIdx.x;
    g_hist[t] = 0u;
    if (t == 0) { g_sum = 0.0; g_sumsq = 0.0; }
}

// ---------------- stage 1: sum / sumsq over ht[0:3] ----------------
__global__ void reduce_kernel(const float4* __restrict__ p) {
    const int M4 = 3 * TABLE_SIZE / 4;
    double s = 0.0, ss = 0.0;
    int stride = gridDim.x * blockDim.x;
    for (int i = blockIdx.x * blockDim.x + threadIdx.x; i < M4; i += stride) {
        float4 v = __ldcs(p + i);   // streaming: don't evict L2
        s  += (double)v.x + (double)v.y + (double)v.z + (double)v.w;
        ss += (double)v.x * v.x + (double)v.y * v.y
            + (double)v.z * v.z + (double)v.w * v.w;
    }
    #pragma unroll
    for (int o = 16; o > 0; o >>= 1) {
        s  += __shfl_down_sync(0xffffffffu, s,  o);
        ss += __shfl_down_sync(0xffffffffu, ss, o);
    }
    __shared__ double sh_s[8], sh_ss[8];
    int w = threadIdx.x >> 5, l = threadIdx.x & 31;
    if (l == 0) { sh_s[w] = s; sh_ss[w] = ss; }
    __syncthreads();
    if (threadIdx.x == 0) {
        double ts = 0.0, tss = 0.0;
        int nw = blockDim.x >> 5;
        for (int k = 0; k < nw; k++) { ts += sh_s[k]; tss += sh_ss[k]; }
        atomicAdd(&g_sum, ts);
        atomicAdd(&g_sumsq, tss);
    }
}

// ---------------- stage 2: finalize stats (ddof=1) ----------------
__global__ void finalize_kernel() {
    const double M = 3.0 * (double)TABLE_SIZE;
    double mean = g_sum / M;
    double var  = (g_sumsq - g_sum * g_sum / M) / (M - 1.0);
    g_mean    = (float)mean;
    g_inv_std = (float)(1.0 / sqrt(var));
}

// ---------------- stage 3: bucket histogram ----------------
__global__ void __launch_bounds__(256)
hist_kernel(const int* __restrict__ coords) {
    __shared__ unsigned sh[NB];
    #pragma unroll
    for (int k = threadIdx.x; k < NB; k += 256) sh[k] = 0u;
    __syncthreads();
    int stride = gridDim.x * blockDim.x;
    for (int i = blockIdx.x * blockDim.x + threadIdx.x; i < NVOX; i += stride) {
        int cx = coords[3*i + 0];
        int cy = coords[3*i + 1];
        int cz = coords[3*i + 2];
        unsigned idx = hash_idx(cx, cy, cz);
        atomicAdd(&sh[idx >> BSHIFT], 1u);
    }
    __syncthreads();
    #pragma unroll
    for (int k = threadIdx.x; k < NB; k += 256)
        if (sh[k]) atomicAdd(&g_hist[k], sh[k]);
}

// ---------------- stage 4: exclusive scan (1024, single block) ----------------
__global__ void scan_kernel() {
    __shared__ unsigned s[NB];
    int t = threadIdx.x;
    unsigned own = g_hist[t];
    s[t] = own;
    __syncthreads();
    for (int off = 1; off < NB; off <<= 1) {
        unsigned v = (t >= off) ? s[t - off] : 0u;
        __syncthreads();
        s[t] += v;
        __syncthreads();
    }
    g_cursor[t] = s[t] - own;   // exclusive prefix
}

// ---------------- stage 5: scatter into bucket order ----------------
__global__ void __launch_bounds__(256)
scatter_kernel(const int* __restrict__ coords) {
    int i = blockIdx.x * blockDim.x + threadIdx.x;
    if (i >= NVOX) return;
    int cx = coords[3*i + 0];   // hits L2 (loaded by hist pass)
    int cy = coords[3*i + 1];
    int cz = coords[3*i + 2];
    unsigned idx = hash_idx(cx, cy, cz);
    unsigned b = idx >> BSHIFT;
    unsigned pos = atomicAdd(&g_cursor[b], 1u);
    unsigned pc = (unsigned)cx | ((unsigned)cy << 7) | ((unsigned)cz << 14);
    g_records[pos] = make_uint2((unsigned)i, pc);
}

// ---------------- stage 6: main per-voxel kernel (bucket order) ----------------
__device__ __forceinline__ float fsigmoid(float x) {
    return 1.0f / (1.0f + __expf(-x));
}

__global__ void __launch_bounds__(256)
voxel_kernel(const float* __restrict__ ht,
             const float* __restrict__ cam,
             const float* __restrict__ far_p,
             const int*   __restrict__ vsz_p,
             float*       __restrict__ out)
{
    int j = blockIdx.x * blockDim.x + threadIdx.x;
    if (j >= NVOX) return;

    uint2 rec = g_records[j];
    unsigned i  = rec.x;
    int cx = (int)( rec.y        & 127u);
    int cy = (int)((rec.y >> 7)  & 127u);
    int cz = (int)((rec.y >> 14) & 127u);
    unsigned idx = hash_idx(cx, cy, cz);

    // gather 14 features (row 14 'curr' never reaches the output)
    float f[14];
    #pragma unroll
    for (int r = 0; r < 14; r++)
        f[r] = __ldg(ht + (size_t)r * TABLE_SIZE + idx);

    float far = __ldg(far_p);
    float vsz = vsz_p ? (float)__ldg(vsz_p) : 128.0f;
    float scale_fac = 2.0f * far / vsz;

    // dmeans: global normalize * scale_fac/6
    float k = g_inv_std * scale_fac * (1.0f / 6.0f);
    float mean = g_mean;
    float d0 = (f[0] - mean) * k;
    float d1 = (f[1] - mean) * k;
    float d2 = (f[2] - mean) * k;

    // voxel center + camera
    float inv_v = 1.0f / vsz;
    float off = far * inv_v - far;
    float m0 = d0 + (float)cx * inv_v * 2.0f * far + off + __ldg(cam + 0);
    float m1 = d1 + (float)cy * inv_v * 2.0f * far + off + __ldg(cam + 1);
    float m2 = d2 + (float)cz * inv_v * 2.0f * far + off + __ldg(cam + 2);

    // quaternion -> rotation
    float qr = f[3], qx = f[4], qy = f[5], qz = f[6];
    float qn = rsqrtf(qr*qr + qx*qx + qy*qy + qz*qz);
    qr *= qn; qx *= qn; qy *= qn; qz *= qn;

    float R00 = 1.0f - 2.0f*(qy*qy + qz*qz);
    float R01 = 2.0f*(qx*qy - qr*qz);
    float R02 = 2.0f*(qx*qz + qr*qy);
    float R10 = 2.0f*(qx*qy + qr*qz);
    float R11 = 1.0f - 2.0f*(qx*qx + qz*qz);
    float R12 = 2.0f*(qy*qz - qr*qx);
    float R20 = 2.0f*(qx*qz - qr*qy);
    float R21 = 2.0f*(qy*qz + qr*qx);
    float R22 = 1.0f - 2.0f*(qx*qx + qy*qy);

    // scales (sigmoid * scale_fac); cov = R diag(s^2) R^T
    float s0 = fsigmoid(f[7]) * scale_fac;
    float s1 = fsigmoid(f[8]) * scale_fac;
    float s2 = fsigmoid(f[9]) * scale_fac;
    float v0 = s0*s0, v1 = s1*s1, v2 = s2*s2;

    float c00 = R00*R00*v0 + R01*R01*v1 + R02*R02*v2;
    float c01 = R00*R10*v0 + R01*R11*v1 + R02*R12*v2;
    float c02 = R00*R20*v0 + R01*R21*v1 + R02*R22*v2;
    float c11 = R10*R10*v0 + R11*R11*v1 + R12*R12*v2;
    float c12 = R10*R20*v0 + R11*R21*v1 + R12*R22*v2;
    float c22 = R20*R20*v0 + R21*R21*v1 + R22*R22*v2;

    float sh0 = fsigmoid(f[10]);
    float sh1 = fsigmoid(f[11]);
    float sh2 = fsigmoid(f[12]);
    float op  = fsigmoid(f[13] - 4.0f);

    // output row i: [m, cov(9), shs(3), opac] — 64B aligned, streaming stores
    float4* o = (float4*)(out + (size_t)i * 16);
    __stcs(o + 0, make_float4(m0,  m1,  m2,  c00));
    __stcs(o + 1, make_float4(c01, c02, c01, c11));
    __stcs(o + 2, make_float4(c12, c02, c12, c22));
    __stcs(o + 3, make_float4(sh0, sh1, sh2, op));
}

// ---------------- launcher ----------------
extern "C" void kernel_launch(void* const* d_in, const int* in_sizes, int n_in,
                              void* d_out, int out_size)
{
    const int*   coords = (const int*)  d_in[0];
    const float* ht     = (const float*)d_in[1];
    const float* cam    = (const float*)d_in[2];
    const float* far_p  = (const float*)d_in[3];
    const int*   vsz_p  = (n_in >= 5) ? (const int*)d_in[4] : nullptr;
    float* out = (float*)d_out;

    zero_kernel<<<1, NB>>>();
    reduce_kernel<<<2048, 256>>>((const float4*)ht);
    hist_kernel<<<512, 256>>>(coords);
    scan_kernel<<<1, NB>>>();
    scatter_kernel<<<(NVOX + 255) / 256, 256>>>(coords);
    finalize_kernel<<<1, 1>>>();
    voxel_kernel<<<(NVOX + 255) / 256, 256>>>(ht, cam, far_p, vsz_p, out);
}

// round 3
// speedup vs baseline: 1.7411x; 1.7411x over previous
#include <cuda_runtime.h>
#include <math.h>

#define TABLE_SIZE 4194304          // 2^22
#define TABLE_MASK (TABLE_SIZE - 1)
#define NVOX (128*128*128)          // 2,097,152
#define NB 1024                     // buckets
#define BSHIFT 12                   // idx >> 12 -> bucket
#define NBLK 256                    // hist/scatter fat blocks
#define CHUNK (NVOX / NBLK)         // 8192 voxels per fat block
#define RGRID 2048                  // reduce grid

// ---------------- device-global scratch (allocation-free) ----------------
__device__ double   g_part_s[RGRID];
__device__ double   g_part_ss[RGRID];
__device__ float    g_mean;
__device__ float    g_inv_std;
__device__ unsigned g_bhist[NBLK * NB];   // 1 MB: per-(block,bucket) counts -> offsets
__device__ unsigned g_base[NB];           // exclusive bucket bases
__device__ uint2    g_records[NVOX];      // (voxel_id, packed coords) 16 MB

__device__ __forceinline__ unsigned hash_idx(int cx, int cy, int cz) {
    unsigned h = (unsigned)cx ^ ((unsigned)cy * 2654435761u)
                             ^ ((unsigned)cz * 805459861u);
    return h & TABLE_MASK;
}

// ---------------- stage 1: sum / sumsq over ht[0:3] (no atomics) ----------------
__global__ void __launch_bounds__(256)
reduce_kernel(const float4* __restrict__ p) {
    const int M4 = 3 * TABLE_SIZE / 4;
    double s = 0.0, ss = 0.0;
    int stride = gridDim.x * blockDim.x;
    for (int i = blockIdx.x * blockDim.x + threadIdx.x; i < M4; i += stride) {
        float4 v = __ldcs(p + i);
        s  += (double)v.x + (double)v.y + (double)v.z + (double)v.w;
        ss += (double)v.x * v.x + (double)v.y * v.y
            + (double)v.z * v.z + (double)v.w * v.w;
    }
    #pragma unroll
    for (int o = 16; o > 0; o >>= 1) {
        s  += __shfl_down_sync(0xffffffffu, s,  o);
        ss += __shfl_down_sync(0xffffffffu, ss, o);
    }
    __shared__ double sh_s[8], sh_ss[8];
    int w = threadIdx.x >> 5, l = threadIdx.x & 31;
    if (l == 0) { sh_s[w] = s; sh_ss[w] = ss; }
    __syncthreads();
    if (threadIdx.x == 0) {
        double ts = 0.0, tss = 0.0;
        for (int k = 0; k < 8; k++) { ts += sh_s[k]; tss += sh_ss[k]; }
        g_part_s[blockIdx.x]  = ts;
        g_part_ss[blockIdx.x] = tss;
    }
}

// ---------------- stage 2: finalize stats (block reduce over partials) ----------------
__global__ void __launch_bounds__(1024)
finalize_kernel() {
    int t = threadIdx.x;
    double s  = g_part_s[t]  + g_part_s[t + 1024];
    double ss = g_part_ss[t] + g_part_ss[t + 1024];
    #pragma unroll
    for (int o = 16; o > 0; o >>= 1) {
        s  += __shfl_down_sync(0xffffffffu, s,  o);
        ss += __shfl_down_sync(0xffffffffu, ss, o);
    }
    __shared__ double sh_s[32], sh_ss[32];
    int w = t >> 5, l = t & 31;
    if (l == 0) { sh_s[w] = s; sh_ss[w] = ss; }
    __syncthreads();
    if (t == 0) {
        double ts = 0.0, tss = 0.0;
        for (int k = 0; k < 32; k++) { ts += sh_s[k]; tss += sh_ss[k]; }
        const double M = 3.0 * (double)TABLE_SIZE;
        double mean = ts / M;
        double var  = (tss - ts * ts / M) / (M - 1.0);
        g_mean    = (float)mean;
        g_inv_std = (float)(1.0 / sqrt(var));
    }
}

// ---------------- stage 3: per-block bucket histograms ----------------
__global__ void __launch_bounds__(256)
hist_kernel(const int* __restrict__ coords) {
    __shared__ unsigned sh[NB];
    #pragma unroll
    for (int k = threadIdx.x; k < NB; k += 256) sh[k] = 0u;
    __syncthreads();
    int base = blockIdx.x * CHUNK;
    for (int v = threadIdx.x; v < CHUNK; v += 256) {
        int i = base + v;
        int cx = coords[3*i + 0];
        int cy = coords[3*i + 1];
        int cz = coords[3*i + 2];
        unsigned idx = hash_idx(cx, cy, cz);
        atomicAdd(&sh[idx >> BSHIFT], 1u);
    }
    __syncthreads();
    unsigned* row = g_bhist + (size_t)blockIdx.x * NB;
    #pragma unroll
    for (int k = threadIdx.x; k < NB; k += 256) row[k] = sh[k];
}

// ---------------- stage 4: per-(block,bucket) exclusive offsets ----------------
__global__ void __launch_bounds__(NB)
offsets_kernel() {
    int k = threadIdx.x;              // bucket / column
    unsigned run = 0;
    #pragma unroll 8
    for (int b = 0; b < NBLK; b++) {  // column-wise exclusive prefix over blocks
        unsigned t = g_bhist[(size_t)b * NB + k];
        g_bhist[(size_t)b * NB + k] = run;
        run += t;
    }
    // 1024-wide exclusive scan of column totals -> bucket bases
    __shared__ unsigned s[NB];
    s[k] = run;
    __syncthreads();
    for (int off = 1; off < NB; off <<= 1) {
        unsigned v = (k >= off) ? s[k - off] : 0u;
        __syncthreads();
        s[k] += v;
        __syncthreads();
    }
    g_base[k] = s[k] - run;
}

// ---------------- stage 5: scatter into bucket order (shared atomics only) ----------------
__global__ void __launch_bounds__(256)
scatter_kernel(const int* __restrict__ coords) {
    __shared__ unsigned cur[NB];
    const unsigned* row = g_bhist + (size_t)blockIdx.x * NB;
    #pragma unroll
    for (int k = threadIdx.x; k < NB; k += 256)
        cur[k] = g_base[k] + row[k];
    __syncthreads();
    int base = blockIdx.x * CHUNK;
    for (int v = threadIdx.x; v < CHUNK; v += 256) {
        int i = base + v;
        int cx = __ldcs(coords + 3*i + 0);
        int cy = __ldcs(coords + 3*i + 1);
        int cz = __ldcs(coords + 3*i + 2);
        unsigned idx = hash_idx(cx, cy, cz);
        unsigned pos = atomicAdd(&cur[idx >> BSHIFT], 1u);
        unsigned pc = (unsigned)cx | ((unsigned)cy << 7) | ((unsigned)cz << 14);
        g_records[pos] = make_uint2((unsigned)i, pc);
    }
}

// ---------------- stage 6: main per-voxel kernel (bucket order) ----------------
__device__ __forceinline__ float fsigmoid(float x) {
    return 1.0f / (1.0f + __expf(-x));
}

__global__ void __launch_bounds__(256)
voxel_kernel(const float* __restrict__ ht,
             const float* __restrict__ cam,
             const float* __restrict__ far_p,
             const int*   __restrict__ vsz_p,
             float*       __restrict__ out)
{
    int j = blockIdx.x * blockDim.x + threadIdx.x;
    if (j >= NVOX) return;

    uint2 rec = g_records[j];
    unsigned i  = rec.x;
    int cx = (int)( rec.y        & 127u);
    int cy = (int)((rec.y >> 7)  & 127u);
    int cz = (int)((rec.y >> 14) & 127u);
    unsigned idx = hash_idx(cx, cy, cz);

    // gather 14 features (row 14 'curr' never reaches the output)
    float f[14];
    #pragma unroll
    for (int r = 0; r < 14; r++)
        f[r] = __ldg(ht + (size_t)r * TABLE_SIZE + idx);

    float far = __ldg(far_p);
    float vsz = vsz_p ? (float)__ldg(vsz_p) : 128.0f;
    float scale_fac = 2.0f * far / vsz;

    // dmeans: global normalize * scale_fac/6
    float k = g_inv_std * scale_fac * (1.0f / 6.0f);
    float mean = g_mean;
    float d0 = (f[0] - mean) * k;
    float d1 = (f[1] - mean) * k;
    float d2 = (f[2] - mean) * k;

    // voxel center + camera
    float inv_v = 1.0f / vsz;
    float off = far * inv_v - far;
    float m0 = d0 + (float)cx * inv_v * 2.0f * far + off + __ldg(cam + 0);
    float m1 = d1 + (float)cy * inv_v * 2.0f * far + off + __ldg(cam + 1);
    float m2 = d2 + (float)cz * inv_v * 2.0f * far + off + __ldg(cam + 2);

    // quaternion -> rotation
    float qr = f[3], qx = f[4], qy = f[5], qz = f[6];
    float qn = rsqrtf(qr*qr + qx*qx + qy*qy + qz*qz);
    qr *= qn; qx *= qn; qy *= qn; qz *= qn;

    float R00 = 1.0f - 2.0f*(qy*qy + qz*qz);
    float R01 = 2.0f*(qx*qy - qr*qz);
    float R02 = 2.0f*(qx*qz + qr*qy);
    float R10 = 2.0f*(qx*qy + qr*qz);
    float R11 = 1.0f - 2.0f*(qx*qx + qz*qz);
    float R12 = 2.0f*(qy*qz - qr*qx);
    float R20 = 2.0f*(qx*qz - qr*qy);
    float R21 = 2.0f*(qy*qz + qr*qx);
    float R22 = 1.0f - 2.0f*(qx*qx + qy*qy);

    // scales (sigmoid * scale_fac); cov = R diag(s^2) R^T
    float s0 = fsigmoid(f[7]) * scale_fac;
    float s1 = fsigmoid(f[8]) * scale_fac;
    float s2 = fsigmoid(f[9]) * scale_fac;
    float v0 = s0*s0, v1 = s1*s1, v2 = s2*s2;

    float c00 = R00*R00*v0 + R01*R01*v1 + R02*R02*v2;
    float c01 = R00*R10*v0 + R01*R11*v1 + R02*R12*v2;
    float c02 = R00*R20*v0 + R01*R21*v1 + R02*R22*v2;
    float c11 = R10*R10*v0 + R11*R11*v1 + R12*R12*v2;
    float c12 = R10*R20*v0 + R11*R21*v1 + R12*R22*v2;
    float c22 = R20*R20*v0 + R21*R21*v1 + R22*R22*v2;

    float sh0 = fsigmoid(f[10]);
    float sh1 = fsigmoid(f[11]);
    float sh2 = fsigmoid(f[12]);
    float op  = fsigmoid(f[13] - 4.0f);

    // output row i: [m, cov(9), shs(3), opac] — 64B aligned, streaming stores
    float4* o = (float4*)(out + (size_t)i * 16);
    __stcs(o + 0, make_float4(m0,  m1,  m2,  c00));
    __stcs(o + 1, make_float4(c01, c02, c01, c11));
    __stcs(o + 2, make_float4(c12, c02, c12, c22));
    __stcs(o + 3, make_float4(sh0, sh1, sh2, op));
}

// ---------------- launcher ----------------
extern "C" void kernel_launch(void* const* d_in, const int* in_sizes, int n_in,
                              void* d_out, int out_size)
{
    const int*   coords = (const int*)  d_in[0];
    const float* ht     = (const float*)d_in[1];
    const float* cam    = (const float*)d_in[2];
    const float* far_p  = (const float*)d_in[3];
    const int*   vsz_p  = (n_in >= 5) ? (const int*)d_in[4] : nullptr;
    float* out = (float*)d_out;

    reduce_kernel<<<RGRID, 256>>>((const float4*)ht);
    hist_kernel<<<NBLK, 256>>>(coords);
    offsets_kernel<<<1, NB>>>();
    scatter_kernel<<<NBLK, 256>>>(coords);
    finalize_kernel<<<1, 1024>>>();
    voxel_kernel<<<(NVOX + 255) / 256, 256>>>(ht, cam, far_p, vsz_p, out);
}

// round 5
// speedup vs baseline: 1.8570x; 1.0665x over previous
#include <cuda_runtime.h>
#include <math.h>

#define TABLE_SIZE 4194304          // 2^22
#define TABLE_MASK (TABLE_SIZE - 1)
#define NVOX (128*128*128)          // 2,097,152
#define NB 1024                     // buckets
#define BSHIFT 12                   // idx >> 12 -> bucket
#define NBLK 256                    // hist/scatter fat blocks
#define CHUNK (NVOX / NBLK)         // 8192 voxels per fat block
#define RGRID 2048                  // reduce grid

// ---------------- device-global scratch (allocation-free) ----------------
__device__ double   g_part_s[RGRID];
__device__ double   g_part_ss[RGRID];
__device__ float    g_mean;
__device__ float    g_inv_std;
__device__ unsigned g_bhist[NBLK * NB];   // 1 MB: per-(block,bucket) counts -> offsets
__device__ unsigned g_base[NB];           // exclusive bucket bases
__device__ uint2    g_records[NVOX];      // (voxel_id, packed coords) 16 MB

__device__ __forceinline__ unsigned hash_idx(int cx, int cy, int cz) {
    unsigned h = (unsigned)cx ^ ((unsigned)cy * 2654435761u)
                             ^ ((unsigned)cz * 805459861u);
    return h & TABLE_MASK;
}

// ---------------- stage 1: sum / sumsq over ht[0:3] (no atomics) ----------------
__global__ void __launch_bounds__(256)
reduce_kernel(const float4* __restrict__ p) {
    const int M4 = 3 * TABLE_SIZE / 4;
    double s = 0.0, ss = 0.0;
    int stride = gridDim.x * blockDim.x;
    for (int i = blockIdx.x * blockDim.x + threadIdx.x; i < M4; i += stride) {
        float4 v = __ldcs(p + i);
        s  += (double)v.x + (double)v.y + (double)v.z + (double)v.w;
        ss += (double)v.x * v.x + (double)v.y * v.y
            + (double)v.z * v.z + (double)v.w * v.w;
    }
    #pragma unroll
    for (int o = 16; o > 0; o >>= 1) {
        s  += __shfl_down_sync(0xffffffffu, s,  o);
        ss += __shfl_down_sync(0xffffffffu, ss, o);
    }
    __shared__ double sh_s[8], sh_ss[8];
    int w = threadIdx.x >> 5, l = threadIdx.x & 31;
    if (l == 0) { sh_s[w] = s; sh_ss[w] = ss; }
    __syncthreads();
    if (threadIdx.x == 0) {
        double ts = 0.0, tss = 0.0;
        for (int k = 0; k < 8; k++) { ts += sh_s[k]; tss += sh_ss[k]; }
        g_part_s[blockIdx.x]  = ts;
        g_part_ss[blockIdx.x] = tss;
    }
}

// ---------------- stage 3: per-block bucket histograms (1024 threads) ----------------
__global__ void __launch_bounds__(1024)
hist_kernel(const int* __restrict__ coords) {
    __shared__ unsigned sh[NB];
    sh[threadIdx.x] = 0u;
    __syncthreads();
    int base = blockIdx.x * CHUNK;
    #pragma unroll 8
    for (int v = threadIdx.x; v < CHUNK; v += 1024) {
        int i = base + v;
        int cx = coords[3*i + 0];
        int cy = coords[3*i + 1];
        int cz = coords[3*i + 2];
        unsigned idx = hash_idx(cx, cy, cz);
        atomicAdd(&sh[idx >> BSHIFT], 1u);
    }
    __syncthreads();
    g_bhist[(size_t)blockIdx.x * NB + threadIdx.x] = sh[threadIdx.x];
}

// ---- stage 4: per-(block,bucket) exclusive offsets + stats finalize (fused) ----
__global__ void __launch_bounds__(NB)
offsets_kernel() {
    int k = threadIdx.x;

    // --- part A: finalize mean/std from reduce partials (all 1024 threads) ---
    {
        double s  = g_part_s[k]  + g_part_s[k + 1024];
        double ss = g_part_ss[k] + g_part_ss[k + 1024];
        #pragma unroll
        for (int o = 16; o > 0; o >>= 1) {
            s  += __shfl_down_sync(0xffffffffu, s,  o);
            ss += __shfl_down_sync(0xffffffffu, ss, o);
        }
        __shared__ double sh_s[32], sh_ss[32];
        int w = k >> 5, l = k & 31;
        if (l == 0) { sh_s[w] = s; sh_ss[w] = ss; }
        __syncthreads();
        if (k == 0) {
            double ts = 0.0, tss = 0.0;
            for (int q = 0; q < 32; q++) { ts += sh_s[q]; tss += sh_ss[q]; }
            const double M = 3.0 * (double)TABLE_SIZE;
            double mean = ts / M;
            double var  = (tss - ts * ts / M) / (M - 1.0);
            g_mean    = (float)mean;
            g_inv_std = (float)(1.0 / sqrt(var));
        }
        __syncthreads();
    }

    // --- part B: column-wise exclusive prefix over blocks ---
    unsigned run = 0;
    #pragma unroll 8
    for (int b = 0; b < NBLK; b++) {
        unsigned t = g_bhist[(size_t)b * NB + k];
        g_bhist[(size_t)b * NB + k] = run;
        run += t;
    }
    // 1024-wide exclusive scan of column totals -> bucket bases
    __shared__ unsigned s[NB];
    s[k] = run;
    __syncthreads();
    for (int off = 1; off < NB; off <<= 1) {
        unsigned v = (k >= off) ? s[k - off] : 0u;
        __syncthreads();
        s[k] += v;
        __syncthreads();
    }
    g_base[k] = s[k] - run;
}

// ---------------- stage 5: scatter into bucket order (1024 threads) ----------------
__global__ void __launch_bounds__(1024)
scatter_kernel(const int* __restrict__ coords) {
    __shared__ unsigned cur[NB];
    cur[threadIdx.x] = g_base[threadIdx.x]
                     + g_bhist[(size_t)blockIdx.x * NB + threadIdx.x];
    __syncthreads();
    int base = blockIdx.x * CHUNK;
    #pragma unroll 8
    for (int v = threadIdx.x; v < CHUNK; v += 1024) {
        int i = base + v;
        int cx = __ldcs(coords + 3*i + 0);
        int cy = __ldcs(coords + 3*i + 1);
        int cz = __ldcs(coords + 3*i + 2);
        unsigned idx = hash_idx(cx, cy, cz);
        unsigned pos = atomicAdd(&cur[idx >> BSHIFT], 1u);
        unsigned pc = (unsigned)cx | ((unsigned)cy << 7) | ((unsigned)cz << 14);
        g_records[pos] = make_uint2((unsigned)i, pc);
    }
}

// ---------------- stage 6: main per-voxel kernel (bucket order, 2/thread) ----------------
__device__ __forceinline__ float fsigmoid(float x) {
    return 1.0f / (1.0f + __expf(-x));
}

__device__ __forceinline__ void
process_one(unsigned i, unsigned pc, const float f[14],
            float scale_fac, float far, float c0, float c1, float c2,
            float mean, float kfac, float* __restrict__ out)
{
    int cx = (int)( pc        & 127u);
    int cy = (int)((pc >> 7)  & 127u);
    int cz = (int)((pc >> 14) & 127u);

    float d0 = (f[0] - mean) * kfac;
    float d1 = (f[1] - mean) * kfac;
    float d2 = (f[2] - mean) * kfac;

    // vc = cx*scale_fac + scale_fac/2 - far + cam
    float off = 0.5f * scale_fac - far;
    float m0 = d0 + (float)cx * scale_fac + off + c0;
    float m1 = d1 + (float)cy * scale_fac + off + c1;
    float m2 = d2 + (float)cz * scale_fac + off + c2;

    float qr = f[3], qx = f[4], qy = f[5], qz = f[6];
    float qn = rsqrtf(qr*qr + qx*qx + qy*qy + qz*qz);
    qr *= qn; qx *= qn; qy *= qn; qz *= qn;

    float R00 = 1.0f - 2.0f*(qy*qy + qz*qz);
    float R01 = 2.0f*(qx*qy - qr*qz);
    float R02 = 2.0f*(qx*qz + qr*qy);
    float R10 = 2.0f*(qx*qy + qr*qz);
    float R11 = 1.0f - 2.0f*(qx*qx + qz*qz);
    float R12 = 2.0f*(qy*qz - qr*qx);
    float R20 = 2.0f*(qx*qz - qr*qy);
    float R21 = 2.0f*(qy*qz + qr*qx);
    float R22 = 1.0f - 2.0f*(qx*qx + qy*qy);

    float s0 = fsigmoid(f[7]) * scale_fac;
    float s1 = fsigmoid(f[8]) * scale_fac;
    float s2 = fsigmoid(f[9]) * scale_fac;
    float v0 = s0*s0, v1 = s1*s1, v2 = s2*s2;

    float c00 = R00*R00*v0 + R01*R01*v1 + R02*R02*v2;
    float c01 = R00*R10*v0 + R01*R11*v1 + R02*R12*v2;
    float c02 = R00*R20*v0 + R01*R21*v1 + R02*R22*v2;
    float c11 = R10*R10*v0 + R11*R11*v1 + R12*R12*v2;
    float c12 = R10*R20*v0 + R11*R21*v1 + R12*R22*v2;
    float c22 = R20*R20*v0 + R21*R21*v1 + R22*R22*v2;

    float sh0 = fsigmoid(f[10]);
    float sh1 = fsigmoid(f[11]);
    float sh2 = fsigmoid(f[12]);
    float op  = fsigmoid(f[13] - 4.0f);

    float4* o = (float4*)(out + (size_t)i * 16);
    __stcs(o + 0, make_float4(m0,  m1,  m2,  c00));
    __stcs(o + 1, make_float4(c01, c02, c01, c11));
    __stcs(o + 2, make_float4(c12, c02, c12, c22));
    __stcs(o + 3, make_float4(sh0, sh1, sh2, op));
}

__global__ void __launch_bounds__(256)
voxel_kernel(const float* __restrict__ ht,
             const float* __restrict__ cam,
             const float* __restrict__ far_p,
             const int*   __restrict__ vsz_p,
             float*       __restrict__ out)
{
    int j2 = blockIdx.x * blockDim.x + threadIdx.x;   // pair index
    if (j2 >= NVOX / 2) return;

    uint4 rr = *(const uint4*)&g_records[(size_t)j2 * 2];
    unsigned iA = rr.x, pcA = rr.y;
    unsigned iB = rr.z, pcB = rr.w;

    unsigned idxA = hash_idx((int)(pcA & 127u), (int)((pcA >> 7) & 127u),
                             (int)((pcA >> 14) & 127u));
    unsigned idxB = hash_idx((int)(pcB & 127u), (int)((pcB >> 7) & 127u),
                             (int)((pcB >> 14) & 127u));

    // issue all 28 gathers up front (max MLP)
    float fA[14], fB[14];
    #pragma unroll
    for (int r = 0; r < 14; r++) {
        fA[r] = __ldg(ht + (size_t)r * TABLE_SIZE + idxA);
        fB[r] = __ldg(ht + (size_t)r * TABLE_SIZE + idxB);
    }

    float far = __ldg(far_p);
    float vsz = vsz_p ? (float)__ldg(vsz_p) : 128.0f;
    float scale_fac = 2.0f * far / vsz;
    float c0 = __ldg(cam + 0), c1 = __ldg(cam + 1), c2 = __ldg(cam + 2);
    float mean = g_mean;
    float kfac = g_inv_std * scale_fac * (1.0f / 6.0f);

    process_one(iA, pcA, fA, scale_fac, far, c0, c1, c2, mean, kfac, out);
    process_one(iB, pcB, fB, scale_fac, far, c0, c1, c2, mean, kfac, out);
}

// ---------------- launcher ----------------
extern "C" void kernel_launch(void* const* d_in, const int* in_sizes, int n_in,
                              void* d_out, int out_size)
{
    const int*   coords = (const int*)  d_in[0];
    const float* ht     = (const float*)d_in[1];
    const float* cam    = (const float*)d_in[2];
    const float* far_p  = (const float*)d_in[3];
    const int*   vsz_p  = (n_in >= 5) ? (const int*)d_in[4] : nullptr;
    float* out = (float*)d_out;

    reduce_kernel<<<RGRID, 256>>>((const float4*)ht);
    hist_kernel<<<NBLK, 1024>>>(coords);
    offsets_kernel<<<1, NB>>>();
    scatter_kernel<<<NBLK, 1024>>>(coords);
    voxel_kernel<<<(NVOX/2 + 255) / 256, 256>>>(ht, cam, far_p, vsz_p, out);
}

// round 6
// speedup vs baseline: 1.8687x; 1.0063x over previous
#include <cuda_runtime.h>
#include <math.h>

#define TABLE_SIZE 4194304          // 2^22
#define TABLE_MASK (TABLE_SIZE - 1)
#define NVOX (128*128*128)          // 2,097,152
#define NB 1024                     // global buckets (idx >> 12)
#define BSHIFT 12
#define NBLK 256                    // hist/scatter fat blocks
#define CHUNK (NVOX / NBLK)         // 8192
#define RB 512                      // reduce blocks inside fused kernel
#define SUBNB 4096                  // in-block sort bins (idx & 4095)
#define CAP 2560                    // max records locally sorted per bucket

// ---------------- device-global scratch (allocation-free) ----------------
__device__ double   g_part_s[RB];
__device__ double   g_part_ss[RB];
__device__ float    g_mean;
__device__ float    g_inv_std;
__device__ unsigned g_bhist[NBLK * NB];   // per-(block,bucket) counts -> offsets
__device__ unsigned g_base[NB];           // exclusive bucket bases
__device__ uint2    g_records[NVOX];      // (voxel_id, packed coords) 16 MB

__device__ __forceinline__ unsigned hash_idx(int cx, int cy, int cz) {
    unsigned h = (unsigned)cx ^ ((unsigned)cy * 2654435761u)
                             ^ ((unsigned)cz * 805459861u);
    return h & TABLE_MASK;
}
__device__ __forceinline__ unsigned hash_pc(unsigned pc) {
    return hash_idx((int)(pc & 127u), (int)((pc >> 7) & 127u),
                    (int)((pc >> 14) & 127u));
}

// ------- stage 1 (fused): table stats reduce + coord bucket histograms -------
__global__ void __launch_bounds__(1024)
reduce_hist_kernel(const float4* __restrict__ p, const int* __restrict__ coords)
{
    if (blockIdx.x < RB) {
        // ---- reduce over ht[0:3] ----
        const int M4 = 3 * TABLE_SIZE / 4;
        double s = 0.0, ss = 0.0;
        int stride = RB * 1024;
        for (int i = blockIdx.x * 1024 + threadIdx.x; i < M4; i += stride) {
            float4 v = __ldcs(p + i);
            s  += (double)v.x + (double)v.y + (double)v.z + (double)v.w;
            ss += (double)v.x * v.x + (double)v.y * v.y
                + (double)v.z * v.z + (double)v.w * v.w;
        }
        #pragma unroll
        for (int o = 16; o > 0; o >>= 1) {
            s  += __shfl_down_sync(0xffffffffu, s,  o);
            ss += __shfl_down_sync(0xffffffffu, ss, o);
        }
        __shared__ double sh_s[32], sh_ss[32];
        int w = threadIdx.x >> 5, l = threadIdx.x & 31;
        if (l == 0) { sh_s[w] = s; sh_ss[w] = ss; }
        __syncthreads();
        if (threadIdx.x == 0) {
            double ts = 0.0, tss = 0.0;
            for (int k = 0; k < 32; k++) { ts += sh_s[k]; tss += sh_ss[k]; }
            g_part_s[blockIdx.x]  = ts;
            g_part_ss[blockIdx.x] = tss;
        }
    } else {
        // ---- per-block bucket histogram ----
        __shared__ unsigned sh[NB];
        sh[threadIdx.x] = 0u;
        __syncthreads();
        int b = blockIdx.x - RB;
        int base = b * CHUNK;
        #pragma unroll 8
        for (int v = threadIdx.x; v < CHUNK; v += 1024) {
            int i = base + v;
            unsigned idx = hash_idx(coords[3*i], coords[3*i+1], coords[3*i+2]);
            atomicAdd(&sh[idx >> BSHIFT], 1u);
        }
        __syncthreads();
        g_bhist[(size_t)b * NB + threadIdx.x] = sh[threadIdx.x];
    }
}

// ---- stage 2: per-(block,bucket) exclusive offsets + stats finalize (fused) ----
__global__ void __launch_bounds__(NB)
offsets_kernel() {
    int k = threadIdx.x;

    // --- part A: finalize mean/std from reduce partials ---
    {
        double s  = (k < RB) ? g_part_s[k]  : 0.0;
        double ss = (k < RB) ? g_part_ss[k] : 0.0;
        #pragma unroll
        for (int o = 16; o > 0; o >>= 1) {
            s  += __shfl_down_sync(0xffffffffu, s,  o);
            ss += __shfl_down_sync(0xffffffffu, ss, o);
        }
        __shared__ double sh_s[32], sh_ss[32];
        int w = k >> 5, l = k & 31;
        if (l == 0) { sh_s[w] = s; sh_ss[w] = ss; }
        __syncthreads();
        if (k == 0) {
            double ts = 0.0, tss = 0.0;
            for (int q = 0; q < 32; q++) { ts += sh_s[q]; tss += sh_ss[q]; }
            const double M = 3.0 * (double)TABLE_SIZE;
            double mean = ts / M;
            double var  = (tss - ts * ts / M) / (M - 1.0);
            g_mean    = (float)mean;
            g_inv_std = (float)(1.0 / sqrt(var));
        }
        __syncthreads();
    }

    // --- part B: column-wise exclusive prefix over blocks ---
    unsigned run = 0;
    #pragma unroll 8
    for (int b = 0; b < NBLK; b++) {
        unsigned t = g_bhist[(size_t)b * NB + k];
        g_bhist[(size_t)b * NB + k] = run;
        run += t;
    }
    __shared__ unsigned s[NB];
    s[k] = run;
    __syncthreads();
    for (int off = 1; off < NB; off <<= 1) {
        unsigned v = (k >= off) ? s[k - off] : 0u;
        __syncthreads();
        s[k] += v;
        __syncthreads();
    }
    g_base[k] = s[k] - run;
}

// ---------------- stage 3: scatter into bucket order ----------------
__global__ void __launch_bounds__(1024)
scatter_kernel(const int* __restrict__ coords) {
    __shared__ unsigned cur[NB];
    cur[threadIdx.x] = g_base[threadIdx.x]
                     + g_bhist[(size_t)blockIdx.x * NB + threadIdx.x];
    __syncthreads();
    int base = blockIdx.x * CHUNK;
    #pragma unroll 8
    for (int v = threadIdx.x; v < CHUNK; v += 1024) {
        int i = base + v;
        int cx = __ldcs(coords + 3*i + 0);
        int cy = __ldcs(coords + 3*i + 1);
        int cz = __ldcs(coords + 3*i + 2);
        unsigned idx = hash_idx(cx, cy, cz);
        unsigned pos = atomicAdd(&cur[idx >> BSHIFT], 1u);
        unsigned pc = (unsigned)cx | ((unsigned)cy << 7) | ((unsigned)cz << 14);
        g_records[pos] = make_uint2((unsigned)i, pc);
    }
}

// ---------------- stage 4: per-bucket local sort + process ----------------
__device__ __forceinline__ float fsigmoid(float x) {
    return 1.0f / (1.0f + __expf(-x));
}

__device__ __forceinline__ void
process_rec(uint2 r, const float* __restrict__ ht,
            float scale_fac, float far, float c0, float c1, float c2,
            float mean, float kfac, float* __restrict__ out)
{
    unsigned i  = r.x;
    unsigned pc = r.y;
    unsigned idx = hash_pc(pc);

    float f[14];
    #pragma unroll
    for (int q = 0; q < 14; q++)
        f[q] = __ldg(ht + (size_t)q * TABLE_SIZE + idx);

    int cx = (int)( pc        & 127u);
    int cy = (int)((pc >> 7)  & 127u);
    int cz = (int)((pc >> 14) & 127u);

    float d0 = (f[0] - mean) * kfac;
    float d1 = (f[1] - mean) * kfac;
    float d2 = (f[2] - mean) * kfac;

    float off = 0.5f * scale_fac - far;
    float m0 = d0 + (float)cx * scale_fac + off + c0;
    float m1 = d1 + (float)cy * scale_fac + off + c1;
    float m2 = d2 + (float)cz * scale_fac + off + c2;

    float qr = f[3], qx = f[4], qy = f[5], qz = f[6];
    float qn = rsqrtf(qr*qr + qx*qx + qy*qy + qz*qz);
    qr *= qn; qx *= qn; qy *= qn; qz *= qn;

    float R00 = 1.0f - 2.0f*(qy*qy + qz*qz);
    float R01 = 2.0f*(qx*qy - qr*qz);
    float R02 = 2.0f*(qx*qz + qr*qy);
    float R10 = 2.0f*(qx*qy + qr*qz);
    float R11 = 1.0f - 2.0f*(qx*qx + qz*qz);
    float R12 = 2.0f*(qy*qz - qr*qx);
    float R20 = 2.0f*(qx*qz - qr*qy);
    float R21 = 2.0f*(qy*qz + qr*qx);
    float R22 = 1.0f - 2.0f*(qx*qx + qy*qy);

    float s0 = fsigmoid(f[7]) * scale_fac;
    float s1 = fsigmoid(f[8]) * scale_fac;
    float s2 = fsigmoid(f[9]) * scale_fac;
    float v0 = s0*s0, v1 = s1*s1, v2 = s2*s2;

    float c00 = R00*R00*v0 + R01*R01*v1 + R02*R02*v2;
    float c01 = R00*R10*v0 + R01*R11*v1 + R02*R12*v2;
    float c02 = R00*R20*v0 + R01*R21*v1 + R02*R22*v2;
    float c11 = R10*R10*v0 + R11*R11*v1 + R12*R12*v2;
    float c12 = R10*R20*v0 + R11*R21*v1 + R12*R22*v2;
    float c22 = R20*R20*v0 + R21*R21*v1 + R22*R22*v2;

    float sh0 = fsigmoid(f[10]);
    float sh1 = fsigmoid(f[11]);
    float sh2 = fsigmoid(f[12]);
    float op  = fsigmoid(f[13] - 4.0f);

    float4* o = (float4*)(out + (size_t)i * 16);
    __stcs(o + 0, make_float4(m0,  m1,  m2,  c00));
    __stcs(o + 1, make_float4(c01, c02, c01, c11));
    __stcs(o + 2, make_float4(c12, c02, c12, c22));
    __stcs(o + 3, make_float4(sh0, sh1, sh2, op));
}

__global__ void __launch_bounds__(512)
voxel_kernel(const float* __restrict__ ht,
             const float* __restrict__ cam,
             const float* __restrict__ far_p,
             const int*   __restrict__ vsz_p,
             float*       __restrict__ out)
{
    __shared__ unsigned cnt[SUBNB];   // 16 KB: per-low-12-bit counters -> offsets
    __shared__ uint2    srec[CAP];    // 20 KB: locally sorted records
    __shared__ unsigned wsum[16];

    int b = blockIdx.x;                       // one bucket per block
    unsigned start = g_base[b];
    unsigned end   = (b == NB - 1) ? NVOX : g_base[b + 1];
    int n  = (int)(end - start);
    int ns = n < CAP ? n : CAP;

    for (int k = threadIdx.x; k < SUBNB; k += 512) cnt[k] = 0u;
    __syncthreads();

    // histogram of low 12 bits
    for (int j = threadIdx.x; j < ns; j += 512) {
        unsigned idx = hash_pc(g_records[start + j].y);
        atomicAdd(&cnt[idx & (SUBNB - 1)], 1u);
    }
    __syncthreads();

    // exclusive scan of 4096 counters: 512 threads x 8 contiguous each
    int base_k = threadIdx.x * 8;
    unsigned loc[8], tsum = 0;
    #pragma unroll
    for (int q = 0; q < 8; q++) { loc[q] = cnt[base_k + q]; tsum += loc[q]; }
    unsigned incl = tsum;
    int lane = threadIdx.x & 31, wid = threadIdx.x >> 5;
    #pragma unroll
    for (int o = 1; o < 32; o <<= 1) {
        unsigned t = __shfl_up_sync(0xffffffffu, incl, o);
        if (lane >= o) incl += t;
    }
    if (lane == 31) wsum[wid] = incl;
    __syncthreads();
    if (threadIdx.x == 0) {
        unsigned run = 0;
        #pragma unroll
        for (int w = 0; w < 16; w++) { unsigned t = wsum[w]; wsum[w] = run; run += t; }
    }
    __syncthreads();
    unsigned run = wsum[wid] + incl - tsum;   // exclusive prefix of this thread's chunk
    #pragma unroll
    for (int q = 0; q < 8; q++) { unsigned t = loc[q]; cnt[base_k + q] = run; run += t; }
    __syncthreads();

    // scatter records into smem, sorted by low 12 bits (=> full idx order in bucket)
    for (int j = threadIdx.x; j < ns; j += 512) {
        uint2 r = g_records[start + j];
        unsigned idx = hash_pc(r.y);
        unsigned pos = atomicAdd(&cnt[idx & (SUBNB - 1)], 1u);
        srec[pos] = r;
    }
    __syncthreads();

    // ---- process (gathers now span ~8 sectors per warp instead of 32) ----
    float far = __ldg(far_p);
    float vsz = vsz_p ? (float)__ldg(vsz_p) : 128.0f;
    float scale_fac = 2.0f * far / vsz;
    float c0 = __ldg(cam + 0), c1 = __ldg(cam + 1), c2 = __ldg(cam + 2);
    float mean = g_mean;
    float kfac = g_inv_std * scale_fac * (1.0f / 6.0f);

    for (int j = threadIdx.x; j < ns; j += 512)
        process_rec(srec[j], ht, scale_fac, far, c0, c1, c2, mean, kfac, out);

    // overflow records (bucket larger than CAP): process unsorted (rare/none)
    for (int j = CAP + threadIdx.x; j < n; j += 512)
        process_rec(g_records[start + j], ht, scale_fac, far, c0, c1, c2,
                    mean, kfac, out);
}

// ---------------- launcher ----------------
extern "C" void kernel_launch(void* const* d_in, const int* in_sizes, int n_in,
                              void* d_out, int out_size)
{
    const int*   coords = (const int*)  d_in[0];
    const float* ht     = (const float*)d_in[1];
    const float* cam    = (const float*)d_in[2];
    const float* far_p  = (const float*)d_in[3];
    const int*   vsz_p  = (n_in >= 5) ? (const int*)d_in[4] : nullptr;
    float* out = (float*)d_out;

    reduce_hist_kernel<<<RB + NBLK, 1024>>>((const float4*)ht, coords);
    offsets_kernel<<<1, NB>>>();
    scatter_kernel<<<NBLK, 1024>>>(coords);
    voxel_kernel<<<NB, 512>>>(ht, cam, far_p, vsz_p, out);
}